// round 11
// baseline (speedup 1.0000x reference)
#include <cuda_runtime.h>
#include <cuda_bf16.h>
#include <cstdint>

#define N_NODES 100000
#define N_EDGES 800000
#define H 128

#define THREADS 256
#define TILE_M 128
#define KPITCH 132                    // tf32 elems per smem row; %32==4 -> conflict-free frags
#define TILEB (128 * KPITCH * 4)      // 67584 B per 128x128 tf32 tile

#define SM_BIAS 0
#define SM_A    2048
#define SM_W(b) (SM_A + TILEB + (b) * TILEB)
#define SMEM_MSG  (SM_W(1) + TILEB)   // 204800 B (A + 2 W buffers)
#define SMEM_SELF (SM_W(0) + TILEB)   // 137216 B (A + 1 W buffer)

#define SCAN_BS 256
#define SCAN_ITEMS 4
#define SCAN_TILE (SCAN_BS * SCAN_ITEMS)
#define SCAN_NB ((N_NODES + SCAN_TILE - 1) / SCAN_TILE)   // 98

__device__ float g_Wh[(size_t)N_NODES * H];
__device__ float g_Wth[(size_t)N_NODES * H];
__device__ float g_acc[(size_t)N_NODES * H];
// CSR build scratch
__device__ int g_cnt_s[N_NODES], g_cnt_d[N_NODES];
__device__ int g_cur_s[N_NODES], g_cur_d[N_NODES];
__device__ int g_off_s[N_NODES + 1], g_off_d[N_NODES + 1];
__device__ int g_nbr_f[N_EDGES], g_nbr_b[N_EDGES];
__device__ int g_bsum[2][SCAN_NB];

__device__ __forceinline__ uint32_t f2tf32(float f) {
    uint32_t r;
    asm("cvt.rna.tf32.f32 %0, %1;" : "=r"(r) : "f"(f));
    return r;
}
__device__ __forceinline__ void mma_tf32(float* c, const uint32_t* a, const uint32_t* b) {
    asm volatile(
        "mma.sync.aligned.m16n8k8.row.col.f32.tf32.tf32.f32 "
        "{%0,%1,%2,%3}, {%4,%5,%6,%7}, {%8,%9}, {%0,%1,%2,%3};"
        : "+f"(c[0]), "+f"(c[1]), "+f"(c[2]), "+f"(c[3])
        : "r"(a[0]), "r"(a[1]), "r"(a[2]), "r"(a[3]), "r"(b[0]), "r"(b[1]));
}

// Stage a 128-row h/W tile as tf32 into smem.
__device__ __forceinline__ void stage_tile_tf32(uint32_t* ws, const float* src,
                                                int rowBase, int tid, bool guard) {
    #pragma unroll
    for (int it = 0; it < 16; ++it) {
        int idx = tid + it * THREADS;
        int r = idx >> 5, k4 = idx & 31;
        float4 v = make_float4(0.f, 0.f, 0.f, 0.f);
        int gr = rowBase + r;
        if (!guard || gr < N_NODES) v = *(const float4*)(src + (size_t)gr * H + k4 * 4);
        uint4 u = make_uint4(f2tf32(v.x), f2tf32(v.y), f2tf32(v.z), f2tf32(v.w));
        *(uint4*)(ws + r * KPITCH + k4 * 4) = u;
    }
}

// Core 128x128x128 tf32 warp-tile compute (8 warps, 32x64 tiles each).
__device__ __forceinline__ void tile_mma_epilogue(
    const uint32_t* hs, const uint32_t* Wc, const float* bsm,
    float* dst, int rowBase, int lane, int wid) {
    const int m0 = (wid & 3) * 32;
    const int n0 = (wid >> 2) * 64;
    const int g = lane >> 2;
    const int t4 = lane & 3;

    float acc[2][8][4];
    #pragma unroll
    for (int i = 0; i < 2; ++i)
        #pragma unroll
        for (int j = 0; j < 8; ++j)
            #pragma unroll
            for (int q = 0; q < 4; ++q) acc[i][j][q] = 0.f;

    #pragma unroll 4
    for (int ks = 0; ks < 16; ++ks) {
        const int k0 = ks * 8;
        uint32_t a[2][4];
        #pragma unroll
        for (int i = 0; i < 2; ++i) {
            const uint32_t* ar = hs + (m0 + 16 * i + g) * KPITCH + k0 + t4;
            a[i][0] = ar[0];
            a[i][1] = ar[8 * KPITCH];
            a[i][2] = ar[4];
            a[i][3] = ar[8 * KPITCH + 4];
        }
        uint32_t b[8][2];
        #pragma unroll
        for (int j = 0; j < 8; ++j) {
            const uint32_t* br = Wc + (n0 + 8 * j + g) * KPITCH + k0 + t4;
            b[j][0] = br[0];
            b[j][1] = br[4];
        }
        #pragma unroll
        for (int i = 0; i < 2; ++i)
            #pragma unroll
            for (int j = 0; j < 8; ++j)
                mma_tf32(acc[i][j], a[i], b[j]);
    }

    #pragma unroll
    for (int i = 0; i < 2; ++i) {
        int r0 = rowBase + m0 + 16 * i + g;
        #pragma unroll
        for (int j = 0; j < 8; ++j) {
            int col = n0 + 8 * j + t4 * 2;
            float bv0 = bsm[col], bv1 = bsm[col + 1];
            if (r0 < N_NODES) {
                float2 o = make_float2(acc[i][j][0] + bv0, acc[i][j][1] + bv1);
                *(float2*)(dst + (size_t)r0 * H + col) = o;
            }
            if (r0 + 8 < N_NODES) {
                float2 o = make_float2(acc[i][j][2] + bv0, acc[i][j][3] + bv1);
                *(float2*)(dst + (size_t)(r0 + 8) * H + col) = o;
            }
        }
    }
}

// ==================== gemm_msg: Wh = h@W^T+b, Wth = h@Wt^T+bt ===============
__global__ __launch_bounds__(THREADS, 1)
void gemm_msg(const float* __restrict__ h,
              const float* __restrict__ W0, const float* __restrict__ b0,
              const float* __restrict__ W1, const float* __restrict__ b1) {
    extern __shared__ char smem[];
    uint32_t* hs = (uint32_t*)(smem + SM_A);
    const int tid = threadIdx.x;
    const int rowBase = blockIdx.x * TILE_M;

    const float* Wg[2] = {W0, W1};
    const float* bg[2] = {b0, b1};

    for (int i = tid; i < 256; i += THREADS)
        *(float*)(smem + SM_BIAS + i * 4) = bg[i >> 7][i & 127];

    stage_tile_tf32(hs, h, rowBase, tid, true);
    stage_tile_tf32((uint32_t*)(smem + SM_W(0)), W0, 0, tid, false);
    __syncthreads();

    #pragma unroll
    for (int w = 0; w < 2; ++w) {
        if (w == 0)
            stage_tile_tf32((uint32_t*)(smem + SM_W(1)), W1, 0, tid, false);
        tile_mma_epilogue(hs, (const uint32_t*)(smem + SM_W(w)),
                          (const float*)(smem + SM_BIAS) + w * 128,
                          w == 0 ? g_Wh : g_Wth, rowBase,
                          tid & 31, tid >> 5);
        __syncthreads();
    }
}

// ==================== gemm_self: out = h@Ws^T + bs ==========================
__global__ __launch_bounds__(THREADS, 1)
void gemm_self(const float* __restrict__ h,
               const float* __restrict__ Ws, const float* __restrict__ bs,
               float* __restrict__ out) {
    extern __shared__ char smem[];
    uint32_t* hs = (uint32_t*)(smem + SM_A);
    const int tid = threadIdx.x;
    const int rowBase = blockIdx.x * TILE_M;

    for (int i = tid; i < 128; i += THREADS)
        *(float*)(smem + SM_BIAS + i * 4) = bs[i];

    stage_tile_tf32(hs, h, rowBase, tid, true);
    stage_tile_tf32((uint32_t*)(smem + SM_W(0)), Ws, 0, tid, false);
    __syncthreads();

    tile_mma_epilogue(hs, (const uint32_t*)(smem + SM_W(0)),
                      (const float*)(smem + SM_BIAS),
                      out, rowBase, tid & 31, tid >> 5);
}

// ========================= CSR build =========================
__global__ void zero_kernel() {
    int i = blockIdx.x * blockDim.x + threadIdx.x;
    if (i < N_NODES) {
        g_cnt_s[i] = 0; g_cnt_d[i] = 0;
        g_cur_s[i] = 0; g_cur_d[i] = 0;
    }
}
__global__ void hist_kernel(const int* __restrict__ esrc, const int* __restrict__ edst) {
    int e = blockIdx.x * blockDim.x + threadIdx.x;
    if (e < N_EDGES) {
        atomicAdd(&g_cnt_s[esrc[e]], 1);
        atomicAdd(&g_cnt_d[edst[e]], 1);
    }
}

__global__ __launch_bounds__(SCAN_BS)
void scanA_kernel() {
    const int arr = blockIdx.y;
    const int* cnt = arr ? g_cnt_d : g_cnt_s;
    int* off = arr ? g_off_d : g_off_s;
    __shared__ int warp_tot[SCAN_BS / 32];

    const int t = threadIdx.x;
    const int lane = t & 31;
    const int wid = t >> 5;
    const int base = blockIdx.x * SCAN_TILE + t * SCAN_ITEMS;

    int v[SCAN_ITEMS];
    int s = 0;
    #pragma unroll
    for (int i = 0; i < SCAN_ITEMS; ++i) {
        v[i] = (base + i < N_NODES) ? cnt[base + i] : 0;
        s += v[i];
    }
    int inc = s;
    #pragma unroll
    for (int o = 1; o < 32; o <<= 1) {
        int n = __shfl_up_sync(0xffffffffu, inc, o);
        if (lane >= o) inc += n;
    }
    if (lane == 31) warp_tot[wid] = inc;
    __syncthreads();
    if (wid == 0) {
        int wv = (lane < SCAN_BS / 32) ? warp_tot[lane] : 0;
        #pragma unroll
        for (int o = 1; o < SCAN_BS / 32; o <<= 1) {
            int n = __shfl_up_sync(0xffffffffu, wv, o);
            if (lane >= o) wv += n;
        }
        if (lane < SCAN_BS / 32) warp_tot[lane] = wv;
    }
    __syncthreads();
    int excl = inc - s + (wid > 0 ? warp_tot[wid - 1] : 0);
    #pragma unroll
    for (int i = 0; i < SCAN_ITEMS; ++i) {
        if (base + i < N_NODES) off[base + i] = excl;
        excl += v[i];
    }
    if (t == SCAN_BS - 1) g_bsum[arr][blockIdx.x] = warp_tot[SCAN_BS / 32 - 1];
}

__global__ __launch_bounds__(128)
void scanB_kernel() {
    const int arr = blockIdx.y;
    __shared__ int sh[128];
    const int t = threadIdx.x;
    int v = (t < SCAN_NB) ? g_bsum[arr][t] : 0;
    int inc = v;
    int lane = t & 31;
    #pragma unroll
    for (int o = 1; o < 32; o <<= 1) {
        int n = __shfl_up_sync(0xffffffffu, inc, o);
        if (lane >= o) inc += n;
    }
    __shared__ int wt[4];
    if (lane == 31) wt[t >> 5] = inc;
    __syncthreads();
    if (t < 4) {
        int wv = wt[t];
        #pragma unroll
        for (int o = 1; o < 4; o <<= 1) {
            int n = __shfl_up_sync(0xfu, wv, o);
            if ((t & 3) >= o) wv += n;
        }
        wt[t] = wv;
    }
    __syncthreads();
    int incl = inc + ((t >> 5) > 0 ? wt[(t >> 5) - 1] : 0);
    if (t < SCAN_NB) sh[t] = incl - v;
    __syncthreads();
    if (t < SCAN_NB) g_bsum[arr][t] = sh[t];
    if (t == 127) {
        int* off = arr ? g_off_d : g_off_s;
        off[N_NODES] = incl;
    }
}

__global__ __launch_bounds__(SCAN_BS)
void scanC_kernel() {
    const int arr = blockIdx.y;
    int* off = arr ? g_off_d : g_off_s;
    const int add = g_bsum[arr][blockIdx.x];
    const int base = blockIdx.x * SCAN_TILE + threadIdx.x * SCAN_ITEMS;
    #pragma unroll
    for (int i = 0; i < SCAN_ITEMS; ++i)
        if (base + i < N_NODES) off[base + i] += add;
}

__global__ void fill_kernel(const int* __restrict__ esrc, const int* __restrict__ edst) {
    int e = blockIdx.x * blockDim.x + threadIdx.x;
    if (e >= N_EDGES) return;
    int s = esrc[e], d = edst[e];
    int ps = g_off_s[s] + atomicAdd(&g_cur_s[s], 1);
    g_nbr_f[ps] = d;
    int pd = g_off_d[d] + atomicAdd(&g_cur_d[d], 1);
    g_nbr_b[pd] = s;
}

// ============ agg: g_acc[n] = sum_fwd Wh[nbr] + sum_bwd Wth[nbr] ============
__global__ __launch_bounds__(256)
void agg_kernel() {
    int node = (blockIdx.x * blockDim.x + threadIdx.x) >> 5;
    int lane = threadIdx.x & 31;
    if (node >= N_NODES) return;

    float4 acc = make_float4(0.f, 0.f, 0.f, 0.f);

    int b0 = g_off_s[node], e0 = g_off_s[node + 1];
    #pragma unroll 4
    for (int e = b0; e < e0; ++e) {
        int nb = g_nbr_f[e];
        float4 v = *(const float4*)(g_Wh + (size_t)nb * H + lane * 4);
        acc.x += v.x; acc.y += v.y; acc.z += v.z; acc.w += v.w;
    }
    int b1 = g_off_d[node], e1 = g_off_d[node + 1];
    #pragma unroll 4
    for (int e = b1; e < e1; ++e) {
        int nb = g_nbr_b[e];
        float4 v = *(const float4*)(g_Wth + (size_t)nb * H + lane * 4);
        acc.x += v.x; acc.y += v.y; acc.z += v.z; acc.w += v.w;
    }
    *(float4*)(g_acc + (size_t)node * H + lane * 4) = acc;
}

// ================= final: out = relu(out + acc) =================
__global__ __launch_bounds__(256)
void final_kernel(float* __restrict__ out) {
    int i = blockIdx.x * blockDim.x + threadIdx.x;
    const int total4 = (N_NODES * H) / 4;
    if (i < total4) {
        float4 a = ((const float4*)g_acc)[i];
        float4 v = ((float4*)out)[i];
        v.x = fmaxf(v.x + a.x, 0.f);
        v.y = fmaxf(v.y + a.y, 0.f);
        v.z = fmaxf(v.z + a.z, 0.f);
        v.w = fmaxf(v.w + a.w, 0.f);
        ((float4*)out)[i] = v;
    }
}

// Streams/events: host handles only, created once.
static cudaStream_t g_s1 = nullptr, g_s2 = nullptr;
static cudaEvent_t g_evFork = nullptr, g_evCsr = nullptr, g_evSelf = nullptr;

extern "C" void kernel_launch(void* const* d_in, const int* in_sizes, int n_in,
                              void* d_out, int out_size) {
    const float* h_n  = (const float*)d_in[0];
    const int*   esrc = (const int*)d_in[1];
    const int*   edst = (const int*)d_in[2];
    const float* W_w  = (const float*)d_in[3];
    const float* W_b  = (const float*)d_in[4];
    const float* Ws_w = (const float*)d_in[5];
    const float* Ws_b = (const float*)d_in[6];
    const float* Wt_w = (const float*)d_in[7];
    const float* Wt_b = (const float*)d_in[8];
    float* out = (float*)d_out;

    if (!g_s1) {
        int loPri, hiPri;
        cudaDeviceGetStreamPriorityRange(&loPri, &hiPri);
        cudaStreamCreateWithFlags(&g_s1, cudaStreamNonBlocking);
        cudaStreamCreateWithPriority(&g_s2, cudaStreamNonBlocking, loPri);
        cudaEventCreateWithFlags(&g_evFork, cudaEventDisableTiming);
        cudaEventCreateWithFlags(&g_evCsr, cudaEventDisableTiming);
        cudaEventCreateWithFlags(&g_evSelf, cudaEventDisableTiming);
        cudaFuncSetAttribute(gemm_msg,
                             cudaFuncAttributeMaxDynamicSharedMemorySize, SMEM_MSG);
        cudaFuncSetAttribute(gemm_self,
                             cudaFuncAttributeMaxDynamicSharedMemorySize, SMEM_SELF);
    }

    const int gemm_blocks = (N_NODES + TILE_M - 1) / TILE_M;   // 782

    // ---- fork ----
    cudaEventRecord(g_evFork, 0);
    cudaStreamWaitEvent(g_s1, g_evFork, 0);
    cudaStreamWaitEvent(g_s2, g_evFork, 0);

    // s1: CSR build chain
    zero_kernel<<<(N_NODES + 255) / 256, 256, 0, g_s1>>>();
    hist_kernel<<<(N_EDGES + 255) / 256, 256, 0, g_s1>>>(esrc, edst);
    {
        dim3 ga(SCAN_NB, 2), gb(1, 2), gc(SCAN_NB, 2);
        scanA_kernel<<<ga, SCAN_BS, 0, g_s1>>>();
        scanB_kernel<<<gb, 128, 0, g_s1>>>();
        scanC_kernel<<<gc, SCAN_BS, 0, g_s1>>>();
    }
    fill_kernel<<<(N_EDGES + 255) / 256, 256, 0, g_s1>>>(esrc, edst);
    cudaEventRecord(g_evCsr, g_s1);

    // s2 (low priority): self-term GEMM -> d_out
    gemm_self<<<gemm_blocks, THREADS, SMEM_SELF, g_s2>>>(h_n, Ws_w, Ws_b, out);
    cudaEventRecord(g_evSelf, g_s2);

    // main: message GEMMs
    gemm_msg<<<gemm_blocks, THREADS, SMEM_MSG>>>(h_n, W_w, W_b, Wt_w, Wt_b);

    // main: aggregate (needs CSR + messages, NOT gemm_self)
    cudaStreamWaitEvent(0, g_evCsr, 0);
    int agg_blocks = (N_NODES * 32 + 255) / 256;               // 12500
    agg_kernel<<<agg_blocks, 256>>>();

    // main: final combine + relu (needs gemm_self + agg)
    cudaStreamWaitEvent(0, g_evSelf, 0);
    int fin_blocks = ((N_NODES * H) / 4 + 255) / 256;
    final_kernel<<<fin_blocks, 256>>>(out);
}

// round 12
// speedup vs baseline: 1.2906x; 1.2906x over previous
#include <cuda_runtime.h>
#include <cuda_bf16.h>
#include <cuda_fp16.h>
#include <cstdint>

#define N_NODES 100000
#define N_EDGES 800000
#define H 128

#define THREADS 256
#define TILE_M 128
#define KPITCH 132                    // tf32 elems per smem row; %32==4 -> conflict-free frags
#define TILEB (128 * KPITCH * 4)      // 67584 B per 128x128 tf32 tile

#define SM_BIAS 0
#define SM_A    2048
#define SM_W(b) (SM_A + TILEB + (b) * TILEB)
#define SMEM_BYTES (SM_W(1) + TILEB)  // 204800 B

#define SCAN_BS 256
#define SCAN_ITEMS 4
#define SCAN_TILE (SCAN_BS * SCAN_ITEMS)
#define SCAN_NB ((N_NODES + SCAN_TILE - 1) / SCAN_TILE)   // 98

// Messages stored as half2 (per node: 64 half2 = 128 halves)
__device__ __half2 g_Wh[(size_t)N_NODES * (H / 2)];
__device__ __half2 g_Wth[(size_t)N_NODES * (H / 2)];
// CSR build scratch
__device__ int g_cnt_s[N_NODES], g_cnt_d[N_NODES];
__device__ int g_cur_s[N_NODES], g_cur_d[N_NODES];
__device__ int g_off_s[N_NODES + 1], g_off_d[N_NODES + 1];
__device__ int g_nbr_f[N_EDGES], g_nbr_b[N_EDGES];
__device__ int g_bsum[2][SCAN_NB];

__device__ __forceinline__ uint32_t f2tf32(float f) {
    uint32_t r;
    asm("cvt.rna.tf32.f32 %0, %1;" : "=r"(r) : "f"(f));
    return r;
}
__device__ __forceinline__ void mma_tf32(float* c, const uint32_t* a, const uint32_t* b) {
    asm volatile(
        "mma.sync.aligned.m16n8k8.row.col.f32.tf32.tf32.f32 "
        "{%0,%1,%2,%3}, {%4,%5,%6,%7}, {%8,%9}, {%0,%1,%2,%3};"
        : "+f"(c[0]), "+f"(c[1]), "+f"(c[2]), "+f"(c[3])
        : "r"(a[0]), "r"(a[1]), "r"(a[2]), "r"(a[3]), "r"(b[0]), "r"(b[1]));
}

// ========================= GEMM (single-pass TF32) ==========================
// w=0 -> g_Wh (fp16), w=1 -> d_out (fp32, Wsh+bias), w=2 -> g_Wth (fp16)
__global__ __launch_bounds__(THREADS, 1)
void gemm3_mma(const float* __restrict__ h,
               const float* __restrict__ W0, const float* __restrict__ b0,
               const float* __restrict__ W1, const float* __restrict__ b1,
               const float* __restrict__ W2, const float* __restrict__ b2,
               float* __restrict__ out_self) {
    extern __shared__ char smem[];
    uint32_t* hs = (uint32_t*)(smem + SM_A);
    const int tid = threadIdx.x;
    const int lane = tid & 31;
    const int wid = tid >> 5;
    const int rowBase = blockIdx.x * TILE_M;

    const float* Wg[3] = {W0, W1, W2};
    const float* bg[3] = {b0, b1, b2};

    for (int i = tid; i < 384; i += THREADS)
        *(float*)(smem + SM_BIAS + i * 4) = bg[i >> 7][i & 127];

    // ---- stage A (h tile) as tf32 ----
    #pragma unroll
    for (int it = 0; it < 16; ++it) {
        int idx = tid + it * THREADS;
        int r = idx >> 5, k4 = idx & 31;
        float4 v = make_float4(0.f, 0.f, 0.f, 0.f);
        int gr = rowBase + r;
        if (gr < N_NODES) v = *(const float4*)(h + (size_t)gr * H + k4 * 4);
        uint4 o = make_uint4(f2tf32(v.x), f2tf32(v.y), f2tf32(v.z), f2tf32(v.w));
        *(uint4*)(hs + r * KPITCH + k4 * 4) = o;
    }
    // ---- stage W0 ----
    {
        uint32_t* ws = (uint32_t*)(smem + SM_W(0));
        #pragma unroll
        for (int it = 0; it < 16; ++it) {
            int idx = tid + it * THREADS;
            int o = idx >> 5, k4 = idx & 31;
            float4 v = *(const float4*)(W0 + o * H + k4 * 4);
            uint4 u = make_uint4(f2tf32(v.x), f2tf32(v.y), f2tf32(v.z), f2tf32(v.w));
            *(uint4*)(ws + o * KPITCH + k4 * 4) = u;
        }
    }
    __syncthreads();

    const int m0 = (wid & 3) * 32;    // warp's 32 output rows
    const int n0 = (wid >> 2) * 64;   // warp's 64 output cols
    const int g = lane >> 2;
    const int t4 = lane & 3;

    #pragma unroll
    for (int w = 0; w < 3; ++w) {
        const int buf = w & 1;
        if (w < 2) {
            const float* W = Wg[w + 1];
            uint32_t* ws = (uint32_t*)(smem + SM_W(buf ^ 1));
            #pragma unroll
            for (int it = 0; it < 16; ++it) {
                int idx = tid + it * THREADS;
                int o = idx >> 5, k4 = idx & 31;
                float4 v = *(const float4*)(W + o * H + k4 * 4);
                uint4 u = make_uint4(f2tf32(v.x), f2tf32(v.y), f2tf32(v.z), f2tf32(v.w));
                *(uint4*)(ws + o * KPITCH + k4 * 4) = u;
            }
        }

        float acc[2][8][4];
        #pragma unroll
        for (int i = 0; i < 2; ++i)
            #pragma unroll
            for (int j = 0; j < 8; ++j)
                #pragma unroll
                for (int q = 0; q < 4; ++q) acc[i][j][q] = 0.f;

        const uint32_t* Wc = (const uint32_t*)(smem + SM_W(buf));

        #pragma unroll 4
        for (int ks = 0; ks < 16; ++ks) {
            const int k0 = ks * 8;
            uint32_t a[2][4];
            #pragma unroll
            for (int i = 0; i < 2; ++i) {
                const uint32_t* ar = hs + (m0 + 16 * i + g) * KPITCH + k0 + t4;
                a[i][0] = ar[0];
                a[i][1] = ar[8 * KPITCH];
                a[i][2] = ar[4];
                a[i][3] = ar[8 * KPITCH + 4];
            }
            uint32_t b[8][2];
            #pragma unroll
            for (int j = 0; j < 8; ++j) {
                const uint32_t* br = Wc + (n0 + 8 * j + g) * KPITCH + k0 + t4;
                b[j][0] = br[0];
                b[j][1] = br[4];
            }
            #pragma unroll
            for (int i = 0; i < 2; ++i)
                #pragma unroll
                for (int j = 0; j < 8; ++j)
                    mma_tf32(acc[i][j], a[i], b[j]);
        }

        const float* bsm = (const float*)(smem + SM_BIAS) + w * 128;
        if (w == 1) {
            // self pass: fp32 to d_out
            #pragma unroll
            for (int i = 0; i < 2; ++i) {
                int r0 = rowBase + m0 + 16 * i + g;
                #pragma unroll
                for (int j = 0; j < 8; ++j) {
                    int col = n0 + 8 * j + t4 * 2;
                    float bv0 = bsm[col], bv1 = bsm[col + 1];
                    if (r0 < N_NODES) {
                        float2 o = make_float2(acc[i][j][0] + bv0, acc[i][j][1] + bv1);
                        *(float2*)(out_self + (size_t)r0 * H + col) = o;
                    }
                    if (r0 + 8 < N_NODES) {
                        float2 o = make_float2(acc[i][j][2] + bv0, acc[i][j][3] + bv1);
                        *(float2*)(out_self + (size_t)(r0 + 8) * H + col) = o;
                    }
                }
            }
        } else {
            // message pass: half2 to g_Wh / g_Wth
            __half2* dst = (w == 0) ? g_Wh : g_Wth;
            #pragma unroll
            for (int i = 0; i < 2; ++i) {
                int r0 = rowBase + m0 + 16 * i + g;
                #pragma unroll
                for (int j = 0; j < 8; ++j) {
                    int col = n0 + 8 * j + t4 * 2;
                    float bv0 = bsm[col], bv1 = bsm[col + 1];
                    if (r0 < N_NODES)
                        dst[(size_t)r0 * (H / 2) + (col >> 1)] =
                            __floats2half2_rn(acc[i][j][0] + bv0, acc[i][j][1] + bv1);
                    if (r0 + 8 < N_NODES)
                        dst[(size_t)(r0 + 8) * (H / 2) + (col >> 1)] =
                            __floats2half2_rn(acc[i][j][2] + bv0, acc[i][j][3] + bv1);
                }
            }
        }
        __syncthreads();
    }
}

// ========================= CSR build =========================
__global__ void zero_kernel() {
    int i = blockIdx.x * blockDim.x + threadIdx.x;
    if (i < N_NODES) {
        g_cnt_s[i] = 0; g_cnt_d[i] = 0;
        g_cur_s[i] = 0; g_cur_d[i] = 0;
    }
}
__global__ void hist_kernel(const int* __restrict__ esrc, const int* __restrict__ edst) {
    int e = blockIdx.x * blockDim.x + threadIdx.x;
    if (e < N_EDGES) {
        atomicAdd(&g_cnt_s[esrc[e]], 1);
        atomicAdd(&g_cnt_d[edst[e]], 1);
    }
}

__global__ __launch_bounds__(SCAN_BS)
void scanA_kernel() {
    const int arr = blockIdx.y;
    const int* cnt = arr ? g_cnt_d : g_cnt_s;
    int* off = arr ? g_off_d : g_off_s;
    __shared__ int warp_tot[SCAN_BS / 32];

    const int t = threadIdx.x;
    const int lane = t & 31;
    const int wid = t >> 5;
    const int base = blockIdx.x * SCAN_TILE + t * SCAN_ITEMS;

    int v[SCAN_ITEMS];
    int s = 0;
    #pragma unroll
    for (int i = 0; i < SCAN_ITEMS; ++i) {
        v[i] = (base + i < N_NODES) ? cnt[base + i] : 0;
        s += v[i];
    }
    int inc = s;
    #pragma unroll
    for (int o = 1; o < 32; o <<= 1) {
        int n = __shfl_up_sync(0xffffffffu, inc, o);
        if (lane >= o) inc += n;
    }
    if (lane == 31) warp_tot[wid] = inc;
    __syncthreads();
    if (wid == 0) {
        int wv = (lane < SCAN_BS / 32) ? warp_tot[lane] : 0;
        #pragma unroll
        for (int o = 1; o < SCAN_BS / 32; o <<= 1) {
            int n = __shfl_up_sync(0xffffffffu, wv, o);
            if (lane >= o) wv += n;
        }
        if (lane < SCAN_BS / 32) warp_tot[lane] = wv;
    }
    __syncthreads();
    int excl = inc - s + (wid > 0 ? warp_tot[wid - 1] : 0);
    #pragma unroll
    for (int i = 0; i < SCAN_ITEMS; ++i) {
        if (base + i < N_NODES) off[base + i] = excl;
        excl += v[i];
    }
    if (t == SCAN_BS - 1) g_bsum[arr][blockIdx.x] = warp_tot[SCAN_BS / 32 - 1];
}

__global__ __launch_bounds__(128)
void scanB_kernel() {
    const int arr = blockIdx.y;
    __shared__ int sh[128];
    const int t = threadIdx.x;
    int v = (t < SCAN_NB) ? g_bsum[arr][t] : 0;
    int inc = v;
    int lane = t & 31;
    #pragma unroll
    for (int o = 1; o < 32; o <<= 1) {
        int n = __shfl_up_sync(0xffffffffu, inc, o);
        if (lane >= o) inc += n;
    }
    __shared__ int wt[4];
    if (lane == 31) wt[t >> 5] = inc;
    __syncthreads();
    if (t < 4) {
        int wv = wt[t];
        #pragma unroll
        for (int o = 1; o < 4; o <<= 1) {
            int n = __shfl_up_sync(0xfu, wv, o);
            if ((t & 3) >= o) wv += n;
        }
        wt[t] = wv;
    }
    __syncthreads();
    int incl = inc + ((t >> 5) > 0 ? wt[(t >> 5) - 1] : 0);
    if (t < SCAN_NB) sh[t] = incl - v;
    __syncthreads();
    if (t < SCAN_NB) g_bsum[arr][t] = sh[t];
    if (t == 127) {
        int* off = arr ? g_off_d : g_off_s;
        off[N_NODES] = incl;
    }
}

__global__ __launch_bounds__(SCAN_BS)
void scanC_kernel() {
    const int arr = blockIdx.y;
    int* off = arr ? g_off_d : g_off_s;
    const int add = g_bsum[arr][blockIdx.x];
    const int base = blockIdx.x * SCAN_TILE + threadIdx.x * SCAN_ITEMS;
    #pragma unroll
    for (int i = 0; i < SCAN_ITEMS; ++i)
        if (base + i < N_NODES) off[base + i] += add;
}

__global__ void fill_kernel(const int* __restrict__ esrc, const int* __restrict__ edst) {
    int e = blockIdx.x * blockDim.x + threadIdx.x;
    if (e >= N_EDGES) return;
    int s = esrc[e], d = edst[e];
    int ps = g_off_s[s] + atomicAdd(&g_cur_s[s], 1);
    g_nbr_f[ps] = d;
    int pd = g_off_d[d] + atomicAdd(&g_cur_d[d], 1);
    g_nbr_b[pd] = s;
}

// ====== agg: out[n] = relu(out[n](=Wsh) + sum_f Wh[nbr] + sum_b Wth[nbr]) ===
// fp16 message gathers, fp32 accumulation.
__global__ __launch_bounds__(256)
void agg_kernel(float* __restrict__ out) {
    int node = (blockIdx.x * blockDim.x + threadIdx.x) >> 5;
    int lane = threadIdx.x & 31;
    if (node >= N_NODES) return;

    float4 acc = *(const float4*)(out + (size_t)node * H + lane * 4);

    int b0 = g_off_s[node], e0 = g_off_s[node + 1];
    #pragma unroll 4
    for (int e = b0; e < e0; ++e) {
        int nb = g_nbr_f[e];
        uint2 u = *(const uint2*)(g_Wh + (size_t)nb * (H / 2) + lane * 2);
        float2 p0 = __half22float2(*(const __half2*)&u.x);
        float2 p1 = __half22float2(*(const __half2*)&u.y);
        acc.x += p0.x; acc.y += p0.y; acc.z += p1.x; acc.w += p1.y;
    }
    int b1 = g_off_d[node], e1 = g_off_d[node + 1];
    #pragma unroll 4
    for (int e = b1; e < e1; ++e) {
        int nb = g_nbr_b[e];
        uint2 u = *(const uint2*)(g_Wth + (size_t)nb * (H / 2) + lane * 2);
        float2 p0 = __half22float2(*(const __half2*)&u.x);
        float2 p1 = __half22float2(*(const __half2*)&u.y);
        acc.x += p0.x; acc.y += p0.y; acc.z += p1.x; acc.w += p1.y;
    }
    acc.x = fmaxf(acc.x, 0.f); acc.y = fmaxf(acc.y, 0.f);
    acc.z = fmaxf(acc.z, 0.f); acc.w = fmaxf(acc.w, 0.f);
    *(float4*)(out + (size_t)node * H + lane * 4) = acc;
}

// Side stream + fork/join events (host handles only; created once)
static cudaStream_t g_s1 = nullptr;
static cudaEvent_t g_evFork = nullptr, g_evJoin = nullptr;

extern "C" void kernel_launch(void* const* d_in, const int* in_sizes, int n_in,
                              void* d_out, int out_size) {
    const float* h_n  = (const float*)d_in[0];
    const int*   esrc = (const int*)d_in[1];
    const int*   edst = (const int*)d_in[2];
    const float* W_w  = (const float*)d_in[3];
    const float* W_b  = (const float*)d_in[4];
    const float* Ws_w = (const float*)d_in[5];
    const float* Ws_b = (const float*)d_in[6];
    const float* Wt_w = (const float*)d_in[7];
    const float* Wt_b = (const float*)d_in[8];
    float* out = (float*)d_out;

    if (!g_s1) {
        cudaStreamCreateWithFlags(&g_s1, cudaStreamNonBlocking);
        cudaEventCreateWithFlags(&g_evFork, cudaEventDisableTiming);
        cudaEventCreateWithFlags(&g_evJoin, cudaEventDisableTiming);
        cudaFuncSetAttribute(gemm3_mma,
                             cudaFuncAttributeMaxDynamicSharedMemorySize, SMEM_BYTES);
    }

    // ---- fork: CSR build on side stream, GEMM on main stream ----
    cudaEventRecord(g_evFork, 0);
    cudaStreamWaitEvent(g_s1, g_evFork, 0);

    zero_kernel<<<(N_NODES + 255) / 256, 256, 0, g_s1>>>();
    hist_kernel<<<(N_EDGES + 255) / 256, 256, 0, g_s1>>>(esrc, edst);
    {
        dim3 ga(SCAN_NB, 2), gb(1, 2), gc(SCAN_NB, 2);
        scanA_kernel<<<ga, SCAN_BS, 0, g_s1>>>();
        scanB_kernel<<<gb, 128, 0, g_s1>>>();
        scanC_kernel<<<gc, SCAN_BS, 0, g_s1>>>();
    }
    fill_kernel<<<(N_EDGES + 255) / 256, 256, 0, g_s1>>>(esrc, edst);

    int gemm_blocks = (N_NODES + TILE_M - 1) / TILE_M;   // 782
    gemm3_mma<<<gemm_blocks, THREADS, SMEM_BYTES>>>(
        h_n, W_w, W_b, Ws_w, Ws_b, Wt_w, Wt_b, out);

    // ---- join: agg needs CSR + messages + self term ----
    cudaEventRecord(g_evJoin, g_s1);
    cudaStreamWaitEvent(0, g_evJoin, 0);

    int agg_blocks = (N_NODES * 32 + 255) / 256;         // 12500
    agg_kernel<<<agg_blocks, 256>>>(out);
}